// round 1
// baseline (speedup 1.0000x reference)
#include <cuda_runtime.h>

// Problem constants
#define BATCH    1024
#define NLAYER   2
#define KTRI     32
#define NFAC     4
#define DIMV     64
#define ROWS     128          // KTRI * NFAC rows per (b, layer)
#define ROWPAD   65           // padded row stride (floats) for h/t tiles -> conflict-free

// Shared layout (in floats)
#define OFF_W1     0                      // [128][64] = 8192
#define OFF_B1     (OFF_W1 + 8192)        // 64
#define OFF_W2     (OFF_B1 + 64)          // 64
#define OFF_H      (OFF_W2 + 64)          // 128*65 = 8320
#define OFF_T      (OFF_H + ROWS*ROWPAD)  // 8320
#define OFF_LOG    (OFF_T + ROWS*ROWPAD)  // 128
#define OFF_WTS    (OFF_LOG + ROWS)       // 128
#define OFF_IDX    (OFF_WTS + ROWS)       // 64 ints
#define SMEM_FLOATS (OFF_IDX + 64)
#define SMEM_BYTES  (SMEM_FLOATS * 4)

// ---- packed f32x2 helpers (PTX-only path; doubles fp32 FMA throughput) ----
__device__ __forceinline__ unsigned long long pk2(float x) {
    unsigned int u = __float_as_uint(x);
    unsigned long long r;
    asm("mov.b64 %0, {%1, %1};" : "=l"(r) : "r"(u));
    return r;
}
__device__ __forceinline__ void fma2(unsigned long long& d,
                                     unsigned long long a,
                                     unsigned long long b) {
    asm("fma.rn.f32x2 %0, %1, %2, %0;" : "+l"(d) : "l"(a), "l"(b));
}
__device__ __forceinline__ float2 unpk2(unsigned long long v) {
    unsigned int lo, hi;
    asm("mov.b64 {%0, %1}, %2;" : "=r"(lo), "=r"(hi) : "l"(v));
    return make_float2(__uint_as_float(lo), __uint_as_float(hi));
}

__global__ void __launch_bounds__(256, 2)
kgat_kernel(const float* __restrict__ node_emb,
            const float* __restrict__ W1,
            const float* __restrict__ b1,
            const float* __restrict__ W2,
            const int*   __restrict__ users,
            const int*   __restrict__ items,
            const int*   __restrict__ users_triple,
            const int*   __restrict__ items_triple,
            float*       __restrict__ out)
{
    extern __shared__ float smem[];
    float* w1_sh  = smem + OFF_W1;
    float* b1_sh  = smem + OFF_B1;
    float* w2_sh  = smem + OFF_W2;
    float* h_sh   = smem + OFF_H;
    float* t_sh   = smem + OFF_T;
    float* log_sh = smem + OFF_LOG;
    float* wts_sh = smem + OFF_WTS;
    int*   idx_sh = reinterpret_cast<int*>(smem + OFF_IDX);

    const int tid = threadIdx.x;
    const int b   = blockIdx.x;   // batch index
    const int tw  = blockIdx.y;   // tower: 0=users, 1=items

    const int* trip  = tw ? items_triple : users_triple;
    const int* idxv  = tw ? items : users;

    // Thread tile mapping for the GEMM
    const int rid = tid >> 3;     // 0..31  -> rows rid*4 .. rid*4+3
    const int cid = tid & 7;      // 0..7   -> col pairs (cc*16 + cid*2, +1), cc=0..3

    // ---- stage weights into shared ----
    {
        const float4* w14 = reinterpret_cast<const float4*>(W1);
        float4* dst = reinterpret_cast<float4*>(w1_sh);
        #pragma unroll
        for (int i = tid; i < 2048; i += 256) dst[i] = w14[i];
        if (tid < 64) { b1_sh[tid] = b1[tid]; w2_sh[tid] = W2[tid]; }
    }

    // ---- origin copy (s = 0 slot of output) ----
    {
        const long org = (long)idxv[b];
        out[(((long)tw * 3 + 0) * BATCH + b) * 256 + tid] =
            node_emb[org * 256 + tid];
    }

    const float4* ne4 = reinterpret_cast<const float4*>(node_emb);

    for (int layer = 0; layer < NLAYER; ++layer) {
        // ---- load h/t indices for this layer ----
        if (tid < 64) {
            const int c = (tid < 32) ? 0 : 2;   // 0=head, 2=tail
            const int k = tid & 31;
            idx_sh[tid] = trip[(((long)b * 3 + c) * NLAYER + layer) * KTRI + k];
        }
        __syncthreads();   // also guards W1 (iter 0) / prior-layer t_sh reuse

        // ---- gather h and t rows (each row = 4 factors * 64 dims = 1KB) ----
        #pragma unroll
        for (int it = 0; it < 16; ++it) {
            const int lin = it * 256 + tid;     // 0..4095
            const int row = lin >> 6;           // 0..63 (32 h rows then 32 t rows)
            const int q   = lin & 63;           // float4 index within row
            const long node = (long)idx_sh[row];
            const float4 v = ne4[node * 64 + q];
            const int k  = row & 31;
            const int f  = q >> 4;
            const int d4 = (q & 15) * 4;
            float* dst = (row < 32 ? h_sh : t_sh) + (k * NFAC + f) * ROWPAD + d4;
            dst[0] = v.x; dst[1] = v.y; dst[2] = v.z; dst[3] = v.w;
        }
        __syncthreads();

        // ---- GEMM: hid(128x64) = relu([h|t] @ W1 + b1); reduce to logits ----
        unsigned long long acc[4][4];
        #pragma unroll
        for (int cc = 0; cc < 4; ++cc) {
            const unsigned long long bp =
                *reinterpret_cast<const unsigned long long*>(&b1_sh[cc * 16 + cid * 2]);
            #pragma unroll
            for (int rr = 0; rr < 4; ++rr) acc[rr][cc] = bp;
        }

        #pragma unroll 1
        for (int half = 0; half < 2; ++half) {
            const float* xbase = half ? t_sh : h_sh;
            const float* wbase = w1_sh + half * 64 * 64;
            #pragma unroll 4
            for (int i = 0; i < 64; ++i) {
                unsigned long long xp[4];
                #pragma unroll
                for (int rr = 0; rr < 4; ++rr)
                    xp[rr] = pk2(xbase[(rid * 4 + rr) * ROWPAD + i]);
                const unsigned long long* wq =
                    reinterpret_cast<const unsigned long long*>(wbase + i * 64);
                #pragma unroll
                for (int cc = 0; cc < 4; ++cc) {
                    const unsigned long long wp = wq[cc * 8 + cid];
                    #pragma unroll
                    for (int rr = 0; rr < 4; ++rr) fma2(acc[rr][cc], xp[rr], wp);
                }
            }
        }

        // epilogue: relu, dot with W2, reduce across the 8 col-threads
        #pragma unroll
        for (int rr = 0; rr < 4; ++rr) {
            float plog = 0.f;
            #pragma unroll
            for (int cc = 0; cc < 4; ++cc) {
                const float2 v = unpk2(acc[rr][cc]);
                const int col = cc * 16 + cid * 2;
                plog += fmaxf(v.x, 0.f) * w2_sh[col]
                      + fmaxf(v.y, 0.f) * w2_sh[col + 1];
            }
            plog += __shfl_xor_sync(0xffffffffu, plog, 1);
            plog += __shfl_xor_sync(0xffffffffu, plog, 2);
            plog += __shfl_xor_sync(0xffffffffu, plog, 4);
            if (cid == 0) log_sh[rid * 4 + rr] = plog;
        }
        __syncthreads();

        // ---- softmax over K=32 per factor (warp f handles factor f) ----
        if (tid < 128) {
            const int f = tid >> 5;         // warp id 0..3
            const int k = tid & 31;         // lane = k
            float lg = log_sh[k * NFAC + f];
            float m = lg;
            #pragma unroll
            for (int off = 16; off; off >>= 1)
                m = fmaxf(m, __shfl_xor_sync(0xffffffffu, m, off));
            const float e = __expf(lg - m);
            float s = e;
            #pragma unroll
            for (int off = 16; off; off >>= 1)
                s += __shfl_xor_sync(0xffffffffu, s, off);
            wts_sh[k * NFAC + f] = e / s;
        }
        __syncthreads();

        // ---- weighted sum over k of t_emb; write layer output ----
        {
            const int f = tid >> 6;         // 0..3
            const int d = tid & 63;         // 0..63
            float a = 0.f;
            #pragma unroll
            for (int k = 0; k < KTRI; ++k)
                a += wts_sh[k * NFAC + f] * t_sh[(k * NFAC + f) * ROWPAD + d];
            out[(((long)tw * 3 + 1 + layer) * BATCH + b) * 256 + f * 64 + d] = a;
        }
        __syncthreads();
    }
}

extern "C" void kernel_launch(void* const* d_in, const int* in_sizes, int n_in,
                              void* d_out, int out_size)
{
    const float* node_emb = (const float*)d_in[0];
    // d_in[1] = relation_emb (unused by the reference computation)
    const float* W1       = (const float*)d_in[2];
    const float* b1       = (const float*)d_in[3];
    const float* W2       = (const float*)d_in[4];
    // d_in[5] = b2 (softmax-shift invariant -> unused)
    const int*   users    = (const int*)d_in[6];
    const int*   items    = (const int*)d_in[7];
    const int*   utrip    = (const int*)d_in[8];
    const int*   itrip    = (const int*)d_in[9];
    float* out = (float*)d_out;

    cudaFuncSetAttribute(kgat_kernel,
                         cudaFuncAttributeMaxDynamicSharedMemorySize, SMEM_BYTES);

    dim3 grid(BATCH, 2);
    kgat_kernel<<<grid, 256, SMEM_BYTES>>>(node_emb, W1, b1, W2,
                                           users, items, utrip, itrip, out);
}

// round 3
// speedup vs baseline: 1.6272x; 1.6272x over previous
#include <cuda_runtime.h>
#include <cuda_fp16.h>
#include <cstdint>

// Problem constants
#define BATCH    1024
#define NLAYER   2
#define KTRI     32
#define NFAC     4
#define ROWS     128            // M
#define HID      64             // N
#define KDIM     128            // K = 2*DIM
#define APAD     136            // A row stride in halves (272 B -> ldmatrix conflict-free)
#define BPAD     72             // B row stride in halves (144 B -> ldmatrix conflict-free)
#define TPAD     65             // fp32 t tile row stride

// ---- shared memory layout (bytes) ----
#define OFF_A      0                          // fp16 A [128][136] = 34816
#define OFF_B      34816                      // fp16 W1 [128][72] = 18432
#define OFF_T      53248                      // fp32 t [128][65]  = 33280
#define OFF_B1     86528                      // 64 f
#define OFF_W2     86784                      // 64 f
#define OFF_LOG    87040                      // 128 f
#define OFF_WTS    87552                      // 128 f
#define OFF_IDX    88064                      // 64 int
#define SMEM_BYTES 88320

__device__ __forceinline__ uint32_t smem_u32(const void* p) {
    uint32_t a;
    asm("{ .reg .u64 t; cvta.to.shared.u64 t, %1; cvt.u32.u64 %0, t; }" : "=r"(a) : "l"(p));
    return a;
}

__device__ __forceinline__ void ldsm_x4(uint32_t& r0, uint32_t& r1, uint32_t& r2,
                                        uint32_t& r3, uint32_t addr) {
    asm volatile("ldmatrix.sync.aligned.m8n8.x4.shared.b16 {%0,%1,%2,%3}, [%4];"
                 : "=r"(r0), "=r"(r1), "=r"(r2), "=r"(r3) : "r"(addr));
}
__device__ __forceinline__ void ldsm_x2t(uint32_t& r0, uint32_t& r1, uint32_t addr) {
    asm volatile("ldmatrix.sync.aligned.m8n8.x2.trans.shared.b16 {%0,%1}, [%2];"
                 : "=r"(r0), "=r"(r1) : "r"(addr));
}
__device__ __forceinline__ void mma16816(float* c, uint32_t a0, uint32_t a1,
                                         uint32_t a2, uint32_t a3,
                                         uint32_t b0, uint32_t b1) {
    asm volatile(
        "mma.sync.aligned.m16n8k16.row.col.f32.f16.f16.f32 "
        "{%0,%1,%2,%3}, {%4,%5,%6,%7}, {%8,%9}, {%0,%1,%2,%3};"
        : "+f"(c[0]), "+f"(c[1]), "+f"(c[2]), "+f"(c[3])
        : "r"(a0), "r"(a1), "r"(a2), "r"(a3), "r"(b0), "r"(b1));
}

__global__ void __launch_bounds__(256, 2)
kgat_hmma_kernel(const float* __restrict__ node_emb,
                 const float* __restrict__ W1,
                 const float* __restrict__ b1,
                 const float* __restrict__ W2,
                 const int*   __restrict__ users,
                 const int*   __restrict__ items,
                 const int*   __restrict__ users_triple,
                 const int*   __restrict__ items_triple,
                 float*       __restrict__ out)
{
    extern __shared__ char smem[];
    __half* a_sh  = reinterpret_cast<__half*>(smem + OFF_A);
    __half* bW_sh = reinterpret_cast<__half*>(smem + OFF_B);
    float*  t_sh  = reinterpret_cast<float*>(smem + OFF_T);
    float*  b1_sh = reinterpret_cast<float*>(smem + OFF_B1);
    float*  w2_sh = reinterpret_cast<float*>(smem + OFF_W2);
    float*  log_sh = reinterpret_cast<float*>(smem + OFF_LOG);
    float*  wts_sh = reinterpret_cast<float*>(smem + OFF_WTS);
    int*    idx_sh = reinterpret_cast<int*>(smem + OFF_IDX);

    const int tid = threadIdx.x;
    const int wid = tid >> 5;
    const int lid = tid & 31;
    const int b   = blockIdx.x;
    const int tw  = blockIdx.y;

    const int* trip = tw ? items_triple : users_triple;
    const int* idxv = tw ? items : users;

    // ---- stage W1 (fp16, [k][n] row-major, padded) + b1/W2 ----
    #pragma unroll 4
    for (int i = tid; i < KDIM * HID; i += 256) {
        const int k = i >> 6, n = i & 63;
        bW_sh[k * BPAD + n] = __float2half_rn(W1[i]);
    }
    if (tid < 64) { b1_sh[tid] = b1[tid]; w2_sh[tid] = W2[tid]; }

    // ---- origin copy (s=0 slot) ----
    {
        const long org = (long)idxv[b];
        out[(((long)tw * 3 + 0) * BATCH + b) * 256 + tid] = node_emb[org * 256 + tid];
    }

    const float4* ne4 = reinterpret_cast<const float4*>(node_emb);
    const uint32_t a_u = smem_u32(a_sh);
    const uint32_t b_u = smem_u32(bW_sh);

    // ldmatrix source addresses (fixed per thread)
    const int g   = lid >> 2;      // 0..7
    const int tig = lid & 3;       // 0..3
    // A: row = 16*wid + (lid&15), col chunk = (lid>>4)*8
    const uint32_t a_addr0 = a_u +
        (uint32_t)(((wid * 16 + (lid & 15)) * APAD + (lid >> 4) * 8) * 2);
    // B: row = (lid&15) within k-tile
    const uint32_t b_addr0 = b_u + (uint32_t)(((lid & 15) * BPAD) * 2);

    for (int layer = 0; layer < NLAYER; ++layer) {
        // ---- indices for this layer ----
        if (tid < 64) {
            const int c = (tid < 32) ? 0 : 2;
            idx_sh[tid] = trip[(((long)b * 3 + c) * NLAYER + layer) * KTRI + (tid & 31)];
        }
        __syncthreads();

        // ---- gather: h/t node rows -> fp16 A tile; t also kept fp32 ----
        #pragma unroll
        for (int it = 0; it < 16; ++it) {
            const int lin = it * 256 + tid;       // 0..4095
            const int row = lin >> 6;             // 0..63  (h:0-31, t:32-63)
            const int q   = lin & 63;             // float4 within 256-float node row
            const long node = (long)idx_sh[row];
            const float4 v = ne4[node * 64 + q];
            const int f  = q >> 4;
            const int d4 = (q & 15) * 4;
            const int arow  = (row & 31) * NFAC + f;        // 0..127
            const int kbase = (row < 32 ? 0 : 64) + d4;

            __half2 p0 = __floats2half2_rn(v.x, v.y);
            __half2 p1 = __floats2half2_rn(v.z, v.w);
            uint2 u;
            u.x = *reinterpret_cast<uint32_t*>(&p0);
            u.y = *reinterpret_cast<uint32_t*>(&p1);
            *reinterpret_cast<uint2*>(&a_sh[arow * APAD + kbase]) = u;

            if (row >= 32) {
                float* dst = t_sh + arow * TPAD + d4;
                dst[0] = v.x; dst[1] = v.y; dst[2] = v.z; dst[3] = v.w;
            }
        }
        __syncthreads();

        // ---- HMMA GEMM: D[128x64] = A[128x128] @ W1[128x64] ----
        float acc[8][4];
        #pragma unroll
        for (int nt = 0; nt < 8; ++nt)
            #pragma unroll
            for (int j = 0; j < 4; ++j) acc[nt][j] = 0.f;

        #pragma unroll
        for (int ks = 0; ks < 8; ++ks) {
            uint32_t a0, a1, a2, a3;
            ldsm_x4(a0, a1, a2, a3, a_addr0 + (uint32_t)(ks * 16 * 2));
            const uint32_t bk = b_addr0 + (uint32_t)(ks * 16 * BPAD * 2);
            #pragma unroll
            for (int nt = 0; nt < 8; ++nt) {
                uint32_t bb0, bb1;
                ldsm_x2t(bb0, bb1, bk + (uint32_t)(nt * 8 * 2));
                mma16816(acc[nt], a0, a1, a2, a3, bb0, bb1);
            }
        }

        // ---- epilogue: relu(D+b1).W2 -> logits ----
        {
            float p0 = 0.f, p1 = 0.f;
            #pragma unroll
            for (int nt = 0; nt < 8; ++nt) {
                #pragma unroll
                for (int j = 0; j < 2; ++j) {
                    const int col = nt * 8 + tig * 2 + j;
                    const float bb = b1_sh[col];
                    const float ww = w2_sh[col];
                    p0 += fmaxf(acc[nt][j] + bb, 0.f) * ww;
                    p1 += fmaxf(acc[nt][2 + j] + bb, 0.f) * ww;
                }
            }
            p0 += __shfl_xor_sync(0xffffffffu, p0, 1);
            p0 += __shfl_xor_sync(0xffffffffu, p0, 2);
            p1 += __shfl_xor_sync(0xffffffffu, p1, 1);
            p1 += __shfl_xor_sync(0xffffffffu, p1, 2);
            if (tig == 0) {
                log_sh[wid * 16 + g]     = p0;
                log_sh[wid * 16 + 8 + g] = p1;
            }
        }
        __syncthreads();

        // ---- softmax over K=32 per factor (warp f) ----
        if (tid < 128) {
            const int f = tid >> 5;
            const int k = tid & 31;
            float lg = log_sh[k * NFAC + f];
            float m = lg;
            #pragma unroll
            for (int off = 16; off; off >>= 1)
                m = fmaxf(m, __shfl_xor_sync(0xffffffffu, m, off));
            const float e = __expf(lg - m);
            float s = e;
            #pragma unroll
            for (int off = 16; off; off >>= 1)
                s += __shfl_xor_sync(0xffffffffu, s, off);
            wts_sh[k * NFAC + f] = e / s;
        }
        __syncthreads();

        // ---- weighted sum over k of exact fp32 t_emb ----
        {
            const int f = tid >> 6;
            const int d = tid & 63;
            float a = 0.f;
            #pragma unroll
            for (int k = 0; k < KTRI; ++k)
                a += wts_sh[k * NFAC + f] * t_sh[(k * NFAC + f) * TPAD + d];
            out[(((long)tw * 3 + 1 + layer) * BATCH + b) * 256 + f * 64 + d] = a;
        }
        __syncthreads();
    }
}

extern "C" void kernel_launch(void* const* d_in, const int* in_sizes, int n_in,
                              void* d_out, int out_size)
{
    const float* node_emb = (const float*)d_in[0];
    const float* W1       = (const float*)d_in[2];
    const float* b1       = (const float*)d_in[3];
    const float* W2       = (const float*)d_in[4];
    const int*   users    = (const int*)d_in[6];
    const int*   items    = (const int*)d_in[7];
    const int*   utrip    = (const int*)d_in[8];
    const int*   itrip    = (const int*)d_in[9];
    float* out = (float*)d_out;

    cudaFuncSetAttribute(kgat_hmma_kernel,
                         cudaFuncAttributeMaxDynamicSharedMemorySize, SMEM_BYTES);

    dim3 grid(BATCH, 2);
    kgat_hmma_kernel<<<grid, 256, SMEM_BYTES>>>(node_emb, W1, b1, W2,
                                                users, items, utrip, itrip, out);
}

// round 4
// speedup vs baseline: 2.4739x; 1.5203x over previous
#include <cuda_runtime.h>
#include <cuda_fp16.h>
#include <cstdint>

// Problem constants
#define BATCH    1024
#define NLAYER   2
#define KTRI     32
#define NFAC     4
#define HID      64             // N
#define KDIM     128            // K = 2*DIM
#define APAD     136            // A row stride (halves): 272 B -> ldmatrix conflict-free
#define BPAD     72             // B row stride (halves): 144 B -> ldmatrix conflict-free

// ---- shared memory layout (bytes) ----
#define OFF_A      0                          // fp16 A [128][136] = 34816
#define OFF_B      34816                      // fp16 W1 [128][72] = 18432
#define OFF_B1     53248                      // 64 f
#define OFF_W2     53504                      // 64 f
#define OFF_LOG    53760                      // 128 f = 512
#define OFF_IDX    54272                      // 64 int = 256
#define SMEM_BYTES 54528                      // -> 4 CTAs/SM

// Pre-converted weights (prep kernel fills these once per replay)
__device__ __align__(16) __half g_w1h[KDIM * BPAD];   // padded fp16 W1
__device__ float g_b1w2[128];                          // b1[0:64], W2[64:128]

__global__ void prep_kernel(const float* __restrict__ W1,
                            const float* __restrict__ b1,
                            const float* __restrict__ W2)
{
    const int tid = threadIdx.x;
    for (int i = tid; i < KDIM * HID; i += 256) {
        const int k = i >> 6, n = i & 63;
        g_w1h[k * BPAD + n] = __float2half_rn(W1[i]);
    }
    if (tid < 64) { g_b1w2[tid] = b1[tid]; g_b1w2[64 + tid] = W2[tid]; }
}

__device__ __forceinline__ uint32_t smem_u32(const void* p) {
    uint32_t a;
    asm("{ .reg .u64 t; cvta.to.shared.u64 t, %1; cvt.u32.u64 %0, t; }" : "=r"(a) : "l"(p));
    return a;
}
__device__ __forceinline__ void ldsm_x4(uint32_t& r0, uint32_t& r1, uint32_t& r2,
                                        uint32_t& r3, uint32_t addr) {
    asm volatile("ldmatrix.sync.aligned.m8n8.x4.shared.b16 {%0,%1,%2,%3}, [%4];"
                 : "=r"(r0), "=r"(r1), "=r"(r2), "=r"(r3) : "r"(addr));
}
__device__ __forceinline__ void ldsm_x2t(uint32_t& r0, uint32_t& r1, uint32_t addr) {
    asm volatile("ldmatrix.sync.aligned.m8n8.x2.trans.shared.b16 {%0,%1}, [%2];"
                 : "=r"(r0), "=r"(r1) : "r"(addr));
}
__device__ __forceinline__ void mma16816(float* c, uint32_t a0, uint32_t a1,
                                         uint32_t a2, uint32_t a3,
                                         uint32_t b0, uint32_t b1) {
    asm volatile(
        "mma.sync.aligned.m16n8k16.row.col.f32.f16.f16.f32 "
        "{%0,%1,%2,%3}, {%4,%5,%6,%7}, {%8,%9}, {%0,%1,%2,%3};"
        : "+f"(c[0]), "+f"(c[1]), "+f"(c[2]), "+f"(c[3])
        : "r"(a0), "r"(a1), "r"(a2), "r"(a3), "r"(b0), "r"(b1));
}

__global__ void __launch_bounds__(256, 4)
kgat_hmma4_kernel(const float* __restrict__ node_emb,
                  const int*   __restrict__ users,
                  const int*   __restrict__ items,
                  const int*   __restrict__ users_triple,
                  const int*   __restrict__ items_triple,
                  float*       __restrict__ out)
{
    extern __shared__ char smem[];
    __half* a_sh   = reinterpret_cast<__half*>(smem + OFF_A);
    float*  b1_sh  = reinterpret_cast<float*>(smem + OFF_B1);
    float*  w2_sh  = reinterpret_cast<float*>(smem + OFF_W2);
    float*  log_sh = reinterpret_cast<float*>(smem + OFF_LOG);
    int*    idx_sh = reinterpret_cast<int*>(smem + OFF_IDX);

    const int tid = threadIdx.x;
    const int wid = tid >> 5;
    const int lid = tid & 31;
    const int b     = blockIdx.x;
    const int tw    = blockIdx.y;
    const int layer = blockIdx.z;

    const int* trip = tw ? items_triple : users_triple;
    const int* idxv = tw ? items : users;

    // ---- stage pre-converted W1 (vector copy) + b1/W2 ----
    {
        const uint4* src = reinterpret_cast<const uint4*>(g_w1h);
        uint4* dst = reinterpret_cast<uint4*>(smem + OFF_B);
        for (int i = tid; i < (KDIM * BPAD) / 8; i += 256) dst[i] = src[i];
        if (tid < 64) { b1_sh[tid] = g_b1w2[tid]; w2_sh[tid] = g_b1w2[64 + tid]; }
    }

    // ---- indices for this layer ----
    if (tid < 64) {
        const int c = (tid < 32) ? 0 : 2;
        idx_sh[tid] = trip[(((long)b * 3 + c) * NLAYER + layer) * KTRI + (tid & 31)];
    }

    // ---- origin copy (layer 0 blocks only) ----
    if (layer == 0) {
        const long org = (long)idxv[b];
        out[(((long)tw * 3 + 0) * BATCH + b) * 256 + tid] = node_emb[org * 256 + tid];
    }
    __syncthreads();

    // ---- gather: h/t node rows -> fp16 A tile ----
    const float4* ne4 = reinterpret_cast<const float4*>(node_emb);
    #pragma unroll 4
    for (int it = 0; it < 16; ++it) {
        const int lin = it * 256 + tid;       // 0..4095
        const int row = lin >> 6;             // 0..63  (h:0-31, t:32-63)
        const int q   = lin & 63;             // float4 within 256-float node row
        const long node = (long)idx_sh[row];
        const float4 v = ne4[node * 64 + q];
        const int f  = q >> 4;
        const int d4 = (q & 15) * 4;
        const int arow  = (row & 31) * NFAC + f;        // 0..127
        const int kbase = (row < 32 ? 0 : 64) + d4;

        __half2 p0 = __floats2half2_rn(v.x, v.y);
        __half2 p1 = __floats2half2_rn(v.z, v.w);
        uint2 u;
        u.x = *reinterpret_cast<uint32_t*>(&p0);
        u.y = *reinterpret_cast<uint32_t*>(&p1);
        *reinterpret_cast<uint2*>(&a_sh[arow * APAD + kbase]) = u;
    }
    __syncthreads();

    // ---- HMMA GEMM (two N-passes, 16 acc regs) + logit epilogue ----
    const uint32_t a_u = smem_u32(smem + OFF_A);
    const uint32_t b_u = smem_u32(smem + OFF_B);
    const int g   = lid >> 2;   // 0..7
    const int tig = lid & 3;    // 0..3
    const uint32_t a_addr0 = a_u +
        (uint32_t)(((wid * 16 + (lid & 15)) * APAD + (lid >> 4) * 8) * 2);
    const uint32_t b_addr0 = b_u + (uint32_t)(((lid & 15) * BPAD) * 2);

    float plog0 = 0.f, plog1 = 0.f;
    #pragma unroll
    for (int half = 0; half < 2; ++half) {
        float acc[4][4];
        #pragma unroll
        for (int nt = 0; nt < 4; ++nt)
            #pragma unroll
            for (int j = 0; j < 4; ++j) acc[nt][j] = 0.f;

        #pragma unroll
        for (int ks = 0; ks < 8; ++ks) {
            uint32_t a0, a1, a2, a3;
            ldsm_x4(a0, a1, a2, a3, a_addr0 + (uint32_t)(ks * 16 * 2));
            const uint32_t bk = b_addr0 + (uint32_t)(ks * 16 * BPAD * 2);
            #pragma unroll
            for (int nt = 0; nt < 4; ++nt) {
                uint32_t bb0, bb1;
                ldsm_x2t(bb0, bb1, bk + (uint32_t)((half * 4 + nt) * 8 * 2));
                mma16816(acc[nt], a0, a1, a2, a3, bb0, bb1);
            }
        }
        #pragma unroll
        for (int nt = 0; nt < 4; ++nt) {
            #pragma unroll
            for (int j = 0; j < 2; ++j) {
                const int col = (half * 4 + nt) * 8 + tig * 2 + j;
                const float bb = b1_sh[col];
                const float ww = w2_sh[col];
                plog0 += fmaxf(acc[nt][j]     + bb, 0.f) * ww;
                plog1 += fmaxf(acc[nt][2 + j] + bb, 0.f) * ww;
            }
        }
    }
    plog0 += __shfl_xor_sync(0xffffffffu, plog0, 1);
    plog0 += __shfl_xor_sync(0xffffffffu, plog0, 2);
    plog1 += __shfl_xor_sync(0xffffffffu, plog1, 1);
    plog1 += __shfl_xor_sync(0xffffffffu, plog1, 2);
    if (tig == 0) {
        log_sh[wid * 16 + g]     = plog0;    // row = wid*16+g
        log_sh[wid * 16 + 8 + g] = plog1;    // row = wid*16+8+g
    }
    __syncthreads();

    // ---- fused softmax (per-warp, lane=k) + weighted sum of fp16 t ----
    {
        const int f     = wid >> 1;            // factor handled by this warp
        const int d     = (wid & 1) * 32 + lid;
        // softmax over K=32 for factor f (lane holds k=lid)
        float lg = log_sh[lid * NFAC + f];
        float m = lg;
        #pragma unroll
        for (int off = 16; off; off >>= 1)
            m = fmaxf(m, __shfl_xor_sync(0xffffffffu, m, off));
        const float e = __expf(lg - m);
        float s = e;
        #pragma unroll
        for (int off = 16; off; off >>= 1)
            s += __shfl_xor_sync(0xffffffffu, s, off);
        const float w = e / s;                 // lane k's weight

        float a = 0.f;
        #pragma unroll
        for (int k = 0; k < KTRI; ++k) {
            const float wk = __shfl_sync(0xffffffffu, w, k);
            const float tv = __half2float(a_sh[(k * NFAC + f) * APAD + 64 + d]);
            a = fmaf(wk, tv, a);
        }
        out[(((long)tw * 3 + 1 + layer) * BATCH + b) * 256 + f * 64 + d] = a;
    }
}

extern "C" void kernel_launch(void* const* d_in, const int* in_sizes, int n_in,
                              void* d_out, int out_size)
{
    const float* node_emb = (const float*)d_in[0];
    const float* W1       = (const float*)d_in[2];
    const float* b1       = (const float*)d_in[3];
    const float* W2       = (const float*)d_in[4];
    const int*   users    = (const int*)d_in[6];
    const int*   items    = (const int*)d_in[7];
    const int*   utrip    = (const int*)d_in[8];
    const int*   itrip    = (const int*)d_in[9];
    float* out = (float*)d_out;

    cudaFuncSetAttribute(kgat_hmma4_kernel,
                         cudaFuncAttributeMaxDynamicSharedMemorySize, SMEM_BYTES);

    prep_kernel<<<1, 256>>>(W1, b1, W2);
    dim3 grid(BATCH, 2, NLAYER);
    kgat_hmma4_kernel<<<grid, 256, SMEM_BYTES>>>(node_emb, users, items,
                                                 utrip, itrip, out);
}

// round 5
// speedup vs baseline: 3.3223x; 1.3429x over previous
#include <cuda_runtime.h>
#include <cuda_fp16.h>
#include <cstdint>

// Problem constants
#define BATCH    1024
#define NLAYER   2
#define KTRI     32
#define NFAC     4
#define HID      64             // N
#define KDIM     128            // K = 2*DIM
#define APAD     136            // A row stride (halves): 272 B -> ldmatrix conflict-free
#define BPAD     72             // B row stride (halves): 144 B -> ldmatrix conflict-free
#define NTILES   (BATCH * 2 * NLAYER)   // 4096
#define GRID     608                     // 4 CTAs/SM * 152 SMs (persistent)

// ---- shared memory layout (bytes) ----
#define OFF_A      0                          // fp16 A [128][136] = 34816
#define OFF_B      34816                      // fp16 W1 [128][72] = 18432
#define OFF_B1     53248                      // 64 f
#define OFF_W2     53504                      // 64 f
#define OFF_LOG    53760                      // 128 f = 512
#define SMEM_BYTES 54272                      // -> 4 CTAs/SM

// Pre-converted weights (prep kernel fills these every replay)
__device__ __align__(16) __half g_w1h[KDIM * BPAD];
__device__ float g_b1w2[128];

__global__ void prep_kernel(const float* __restrict__ W1,
                            const float* __restrict__ b1,
                            const float* __restrict__ W2)
{
    const int tid = threadIdx.x;
    for (int i = tid; i < KDIM * HID; i += 256) {
        const int k = i >> 6, n = i & 63;
        g_w1h[k * BPAD + n] = __float2half_rn(W1[i]);
    }
    if (tid < 64) { g_b1w2[tid] = b1[tid]; g_b1w2[64 + tid] = W2[tid]; }
}

__device__ __forceinline__ uint32_t smem_u32(const void* p) {
    uint32_t a;
    asm("{ .reg .u64 t; cvta.to.shared.u64 t, %1; cvt.u32.u64 %0, t; }" : "=r"(a) : "l"(p));
    return a;
}
__device__ __forceinline__ void ldsm_x4(uint32_t& r0, uint32_t& r1, uint32_t& r2,
                                        uint32_t& r3, uint32_t addr) {
    asm volatile("ldmatrix.sync.aligned.m8n8.x4.shared.b16 {%0,%1,%2,%3}, [%4];"
                 : "=r"(r0), "=r"(r1), "=r"(r2), "=r"(r3) : "r"(addr));
}
__device__ __forceinline__ void ldsm_x2t(uint32_t& r0, uint32_t& r1, uint32_t addr) {
    asm volatile("ldmatrix.sync.aligned.m8n8.x2.trans.shared.b16 {%0,%1}, [%2];"
                 : "=r"(r0), "=r"(r1) : "r"(addr));
}
__device__ __forceinline__ void mma16816(float* c, uint32_t a0, uint32_t a1,
                                         uint32_t a2, uint32_t a3,
                                         uint32_t b0, uint32_t b1) {
    asm volatile(
        "mma.sync.aligned.m16n8k16.row.col.f32.f16.f16.f32 "
        "{%0,%1,%2,%3}, {%4,%5,%6,%7}, {%8,%9}, {%0,%1,%2,%3};"
        : "+f"(c[0]), "+f"(c[1]), "+f"(c[2]), "+f"(c[3])
        : "r"(a0), "r"(a1), "r"(a2), "r"(a3), "r"(b0), "r"(b1));
}

// Load this warp's 8 triple indices for a tile (lanes 0-7), else 0.
__device__ __forceinline__ int load_idx8(const int* __restrict__ users_triple,
                                         const int* __restrict__ items_triple,
                                         int tile, int wid, int lid)
{
    if (lid >= 8) return 0;
    const int b     = tile & (BATCH - 1);
    const int tw    = (tile >> 10) & 1;
    const int layer = tile >> 11;
    const int* trip = tw ? items_triple : users_triple;
    const int c = (lid < 4) ? 0 : 2;                    // head / tail
    const int k = wid * 4 + (lid & 3);
    return trip[(((long)b * 3 + c) * NLAYER + layer) * KTRI + k];
}

__global__ void __launch_bounds__(256, 4)
kgat_pers_kernel(const float* __restrict__ node_emb,
                 const int*   __restrict__ users,
                 const int*   __restrict__ items,
                 const int*   __restrict__ users_triple,
                 const int*   __restrict__ items_triple,
                 float*       __restrict__ out)
{
    extern __shared__ char smem[];
    __half* a_sh   = reinterpret_cast<__half*>(smem + OFF_A);
    float*  b1_sh  = reinterpret_cast<float*>(smem + OFF_B1);
    float*  w2_sh  = reinterpret_cast<float*>(smem + OFF_W2);
    float*  log_sh = reinterpret_cast<float*>(smem + OFF_LOG);

    const int tid = threadIdx.x;
    const int wid = tid >> 5;
    const int lid = tid & 31;

    // ---- stage W1 + b1/W2 once per persistent CTA ----
    {
        const uint4* src = reinterpret_cast<const uint4*>(g_w1h);
        uint4* dst = reinterpret_cast<uint4*>(smem + OFF_B);
        for (int i = tid; i < (KDIM * BPAD) / 8; i += 256) dst[i] = src[i];
        if (tid < 64) { b1_sh[tid] = g_b1w2[tid]; w2_sh[tid] = g_b1w2[64 + tid]; }
    }
    __syncthreads();

    const float4* ne4 = reinterpret_cast<const float4*>(node_emb);
    const uint32_t a_u = smem_u32(smem + OFF_A);
    const uint32_t b_u = smem_u32(smem + OFF_B);
    const int g   = lid >> 2;
    const int tig = lid & 3;
    const uint32_t a_addr0 = a_u +
        (uint32_t)(((wid * 16 + (lid & 15)) * APAD + (lid >> 4) * 8) * 2);
    const uint32_t b_addr0 = b_u + (uint32_t)(((lid & 15) * BPAD) * 2);

    int tile = blockIdx.x;
    int idx_pref = (tile < NTILES)
        ? load_idx8(users_triple, items_triple, tile, wid, lid) : 0;

    for (; tile < NTILES; tile += GRID) {
        const int b     = tile & (BATCH - 1);
        const int tw    = (tile >> 10) & 1;
        const int layer = tile >> 11;
        const int idx   = idx_pref;

        // ---- origin copy (layer-0 tiles) ----
        if (layer == 0) {
            const int* idxv = tw ? items : users;
            const long org = (long)idxv[b];
            out[(((long)tw * 3 + 0) * BATCH + b) * 256 + tid] =
                node_emb[org * 256 + tid];
        }

        // ---- warp-local gather: own 8 node rows -> own 16 A rows (fp16) ----
        #pragma unroll 4
        for (int it = 0; it < 16; ++it) {
            const int r = it >> 1;                  // local row 0..7 (h:0-3, t:4-7)
            const int q = (it & 1) * 32 + lid;      // float4 index in node row
            const long node = (long)__shfl_sync(0xffffffffu, idx, r);
            const float4 v = ne4[node * 64 + q];
            const int f  = q >> 4;
            const int d4 = (q & 15) * 4;
            const int arow  = wid * 16 + (r & 3) * 4 + f;
            const int kbase = (r < 4 ? 0 : 64) + d4;

            __half2 p0 = __floats2half2_rn(v.x, v.y);
            __half2 p1 = __floats2half2_rn(v.z, v.w);
            uint2 u;
            u.x = *reinterpret_cast<uint32_t*>(&p0);
            u.y = *reinterpret_cast<uint32_t*>(&p1);
            *reinterpret_cast<uint2*>(&a_sh[arow * APAD + kbase]) = u;
        }

        // ---- prefetch next tile's indices (hidden under MMA) ----
        {
            const int nt_ = tile + GRID;
            idx_pref = (nt_ < NTILES)
                ? load_idx8(users_triple, items_triple, nt_, wid, lid) : 0;
        }

        __syncwarp();   // own A rows visible to own ldmatrix

        // ---- HMMA GEMM (two N-passes) + fused logit epilogue ----
        float plog0 = 0.f, plog1 = 0.f;
        #pragma unroll
        for (int half = 0; half < 2; ++half) {
            float acc[4][4];
            #pragma unroll
            for (int nt = 0; nt < 4; ++nt)
                #pragma unroll
                for (int j = 0; j < 4; ++j) acc[nt][j] = 0.f;

            #pragma unroll
            for (int ks = 0; ks < 8; ++ks) {
                uint32_t a0, a1, a2, a3;
                ldsm_x4(a0, a1, a2, a3, a_addr0 + (uint32_t)(ks * 16 * 2));
                const uint32_t bk = b_addr0 + (uint32_t)(ks * 16 * BPAD * 2);
                #pragma unroll
                for (int nt = 0; nt < 4; ++nt) {
                    uint32_t bb0, bb1;
                    ldsm_x2t(bb0, bb1, bk + (uint32_t)((half * 4 + nt) * 8 * 2));
                    mma16816(acc[nt], a0, a1, a2, a3, bb0, bb1);
                }
            }
            #pragma unroll
            for (int nt = 0; nt < 4; ++nt) {
                #pragma unroll
                for (int j = 0; j < 2; ++j) {
                    const int col = (half * 4 + nt) * 8 + tig * 2 + j;
                    const float bb = b1_sh[col];
                    const float ww = w2_sh[col];
                    plog0 += fmaxf(acc[nt][j]     + bb, 0.f) * ww;
                    plog1 += fmaxf(acc[nt][2 + j] + bb, 0.f) * ww;
                }
            }
        }
        plog0 += __shfl_xor_sync(0xffffffffu, plog0, 1);
        plog0 += __shfl_xor_sync(0xffffffffu, plog0, 2);
        plog1 += __shfl_xor_sync(0xffffffffu, plog1, 1);
        plog1 += __shfl_xor_sync(0xffffffffu, plog1, 2);
        if (tig == 0) {
            log_sh[wid * 16 + g]     = plog0;
            log_sh[wid * 16 + 8 + g] = plog1;
        }
        __syncthreads();

        // ---- softmax + weighted sum (warps 0-3; f = wid, half2 over d) ----
        if (wid < 4) {
            const int f = wid;
            float lg = log_sh[lid * NFAC + f];      // lane = k
            float m = lg;
            #pragma unroll
            for (int off = 16; off; off >>= 1)
                m = fmaxf(m, __shfl_xor_sync(0xffffffffu, m, off));
            const float e = __expf(lg - m);
            float s = e;
            #pragma unroll
            for (int off = 16; off; off >>= 1)
                s += __shfl_xor_sync(0xffffffffu, s, off);
            const float w = e / s;

            float ax = 0.f, ay = 0.f;
            #pragma unroll
            for (int k = 0; k < KTRI; ++k) {
                const float wk = __shfl_sync(0xffffffffu, w, k);
                const __half2 tv = *reinterpret_cast<const __half2*>(
                    &a_sh[(k * NFAC + f) * APAD + 64 + 2 * lid]);
                const float2 tf = __half22float2(tv);
                ax = fmaf(wk, tf.x, ax);
                ay = fmaf(wk, tf.y, ay);
            }
            float2 res = make_float2(ax, ay);
            *reinterpret_cast<float2*>(
                &out[(((long)tw * 3 + 1 + layer) * BATCH + b) * 256
                     + f * 64 + 2 * lid]) = res;
        }
        __syncthreads();   // protect A/log_sh before next tile overwrites
    }
}

extern "C" void kernel_launch(void* const* d_in, const int* in_sizes, int n_in,
                              void* d_out, int out_size)
{
    const float* node_emb = (const float*)d_in[0];
    const float* W1       = (const float*)d_in[2];
    const float* b1       = (const float*)d_in[3];
    const float* W2       = (const float*)d_in[4];
    const int*   users    = (const int*)d_in[6];
    const int*   items    = (const int*)d_in[7];
    const int*   utrip    = (const int*)d_in[8];
    const int*   itrip    = (const int*)d_in[9];
    float* out = (float*)d_out;

    cudaFuncSetAttribute(kgat_pers_kernel,
                         cudaFuncAttributeMaxDynamicSharedMemorySize, SMEM_BYTES);

    prep_kernel<<<1, 256>>>(W1, b1, W2);
    kgat_pers_kernel<<<GRID, 256, SMEM_BYTES>>>(node_emb, users, items,
                                                utrip, itrip, out);
}